// round 15
// baseline (speedup 1.0000x reference)
#include <cuda_runtime.h>
#include <cuda_bf16.h>
#include <cstdint>

#define NRES 512
#define DCH  128
#define NPOS (NRES*NRES)

// Scratch (device globals — no runtime allocation allowed)
__device__ float g_gate [(size_t)NPOS * DCH];        // gate, [d][pos] after gate1
__device__ __nv_bfloat16 g_Xh[(size_t)NPOS * DCH];   // LN(x) [pos][d]; later PRE hi [d][pos]
__device__ __nv_bfloat16 g_Xl[(size_t)NPOS * DCH];   // LN(x) lo;      later PRE lo [d][pos]
__device__ __nv_bfloat16 g_Lh[(size_t)DCH * NPOS];   // left  [d][i][j]
__device__ __nv_bfloat16 g_Ll[(size_t)DCH * NPOS];
__device__ __nv_bfloat16 g_Rh[(size_t)DCH * NPOS];   // right [d][k][j]
__device__ __nv_bfloat16 g_Rl[(size_t)DCH * NPOS];
__device__ __nv_bfloat16 g_Wth[6 * DCH * DCH];       // W^T hi, [widx][n][k]
__device__ __nv_bfloat16 g_Wtl[6 * DCH * DCH];       // W^T lo

__device__ __forceinline__ float fsig(float x) { return 1.0f / (1.0f + __expf(-x)); }

__device__ __forceinline__ void cp16(void* s, const void* g) {
    unsigned sa = (unsigned)__cvta_generic_to_shared(s);
    asm volatile("cp.async.cg.shared.global [%0], [%1], 16;" :: "r"(sa), "l"(g));
}

// ---- mma.sync / ldmatrix (sm_80-class PTX: compiles on plain sm_103) ------
__device__ __forceinline__ void ldsm_x4(uint32_t* r, uint32_t addr) {
    asm volatile("ldmatrix.sync.aligned.m8n8.x4.shared.b16 {%0,%1,%2,%3}, [%4];"
        : "=r"(r[0]), "=r"(r[1]), "=r"(r[2]), "=r"(r[3]) : "r"(addr));
}
__device__ __forceinline__ void ldsm_x4t(uint32_t* r, uint32_t addr) {
    asm volatile("ldmatrix.sync.aligned.m8n8.x4.trans.shared.b16 {%0,%1,%2,%3}, [%4];"
        : "=r"(r[0]), "=r"(r[1]), "=r"(r[2]), "=r"(r[3]) : "r"(addr));
}
__device__ __forceinline__ void ldsm_x2(uint32_t* r, uint32_t addr) {
    asm volatile("ldmatrix.sync.aligned.m8n8.x2.shared.b16 {%0,%1}, [%2];"
        : "=r"(r[0]), "=r"(r[1]) : "r"(addr));
}
__device__ __forceinline__ void mma16816(float* c, const uint32_t* a, const uint32_t* b) {
    asm volatile("mma.sync.aligned.m16n8k16.row.col.f32.bf16.bf16.f32 "
        "{%0,%1,%2,%3}, {%4,%5,%6,%7}, {%8,%9}, {%0,%1,%2,%3};"
        : "+f"(c[0]), "+f"(c[1]), "+f"(c[2]), "+f"(c[3])
        : "r"(a[0]), "r"(a[1]), "r"(a[2]), "r"(a[3]), "r"(b[0]), "r"(b[1]));
}
// C += Ah*Bh + Ah*Bl + Al*Bh   (bf16 hi/lo split product)
__device__ __forceinline__ void mma3(float* c, const uint32_t* aH, const uint32_t* aL,
                                     uint32_t bh0, uint32_t bh1,
                                     uint32_t bl0, uint32_t bl1) {
    uint32_t b[2];
    b[0] = bh0; b[1] = bh1; mma16816(c, aH, b);
    b[0] = bl0; b[1] = bl1; mma16816(c, aH, b);
    b[0] = bh0; b[1] = bh1; mma16816(c, aL, b);
}
// C += Ah*Bh only (single product; sigmoid-gate logits)
__device__ __forceinline__ void mma1(float* c, const uint32_t* aH,
                                     uint32_t b0, uint32_t b1) {
    uint32_t b[2];
    b[0] = b0; b[1] = b1; mma16816(c, aH, b);
}

__device__ __forceinline__ void bsplit(float v, __nv_bfloat16& h, __nv_bfloat16& l) {
    h = __float2bfloat16(v);
    l = __float2bfloat16(v - __bfloat162float(h));
}
__device__ __forceinline__ uint32_t pack2(__nv_bfloat16 a, __nv_bfloat16 b) {
    __nv_bfloat162 p(a, b);
    return *reinterpret_cast<uint32_t*>(&p);
}

// ---------------------------------------------------------------------------
// K0: weight prep — W[k][n] -> Wt_h/Wt_l[n][k] bf16. One block per matrix.
// ---------------------------------------------------------------------------
__global__ void prep_weights(const float* w0, const float* w1, const float* w2,
                             const float* w3, const float* w4, const float* w5)
{
    const float* srcs[6] = {w0, w1, w2, w3, w4, w5};
    const float* src = srcs[blockIdx.x];
    const int base = blockIdx.x * DCH * DCH;
    for (int idx = threadIdx.x; idx < DCH * DCH; idx += blockDim.x) {
        int k = idx >> 7, n = idx & 127;
        __nv_bfloat16 h, l;
        bsplit(src[idx], h, l);
        g_Wth[base + n * DCH + k] = h;
        g_Wtl[base + n * DCH + k] = l;
    }
}

// ---------------------------------------------------------------------------
// K1: LayerNorm over D=128 -> Xh/Xl bf16 [pos][d].
// ---------------------------------------------------------------------------
__global__ void ln_split_kernel(const float* __restrict__ pair,
                                const float* __restrict__ lng,
                                const float* __restrict__ lnb)
{
    const int lane = threadIdx.x & 31;
    const int row  = blockIdx.x * 8 + (threadIdx.x >> 5);
    const float4 v = reinterpret_cast<const float4*>(pair)[(size_t)row * 32 + lane];
    float s = v.x + v.y + v.z + v.w;
    float q = v.x*v.x + v.y*v.y + v.z*v.z + v.w*v.w;
#pragma unroll
    for (int o = 16; o > 0; o >>= 1) {
        s += __shfl_xor_sync(0xffffffffu, s, o);
        q += __shfl_xor_sync(0xffffffffu, q, o);
    }
    const float mean = s * (1.0f / 128.0f);
    const float var  = q * (1.0f / 128.0f) - mean * mean;
    const float rs   = rsqrtf(var + 1e-5f);
    const float4 g4 = reinterpret_cast<const float4*>(lng)[lane];
    const float4 b4 = reinterpret_cast<const float4*>(lnb)[lane];
    float o0 = (v.x - mean) * rs * g4.x + b4.x;
    float o1 = (v.y - mean) * rs * g4.y + b4.y;
    float o2 = (v.z - mean) * rs * g4.z + b4.z;
    float o3 = (v.w - mean) * rs * g4.w + b4.w;
    __nv_bfloat16 h0,l0,h1,l1,h2,l2,h3,l3;
    bsplit(o0,h0,l0); bsplit(o1,h1,l1); bsplit(o2,h2,l2); bsplit(o3,h3,l3);
    uint2 hv = make_uint2(pack2(h0,h1), pack2(h2,h3));
    uint2 lv = make_uint2(pack2(l0,l1), pack2(l2,l3));
    *reinterpret_cast<uint2*>(&g_Xh[(size_t)row * DCH + lane * 4]) = hv;
    *reinterpret_cast<uint2*>(&g_Xl[(size_t)row * DCH + lane * 4]) = lv;
}

// ---------------------------------------------------------------------------
// Projection GEMMs on mma.sync. M tile 64 x N 128, K=128 in 4 stages of 32.
// 8 warps = 4M x 2N, warp = 16 rows x 64 cols.
// ---------------------------------------------------------------------------
#define PJ_RS      80
#define PJ_A_T     (64 * PJ_RS)               // 5120
#define PJ_B_T     (128 * PJ_RS)              // 10240
#define PJ_STAGE_D (2*PJ_A_T + 3*PJ_B_T)      // 40960 (P hi/lo + G hi only)
#define PJ_SMEM_D  (2 * PJ_STAGE_D)           // 81920
#define PJ_STAGE_S1 (PJ_A_T + PJ_B_T)         // 15360
#define PJ_SMEM_S1  (64 * 129 * 4)            // 33024 (> 2*PJ_STAGE_S1, scratch)

// dual: v = (X@Wp + bp) * sigmoid(X@Wg + bg) * mask, hi/lo split + transpose
// (unchanged from R13). DST 0 -> g_Lh/g_Ll [d][i][j]; DST 1 -> g_Rh/g_Rl [d][k][j].
template<int WP, int WG, int DST>
__global__ __launch_bounds__(256, 2) void proj_dual_mma(
    const float* __restrict__ bp, const float* __restrict__ bg,
    const float* __restrict__ mask)
{
    extern __shared__ char smem[];
    const uint32_t sbase = (uint32_t)__cvta_generic_to_shared(smem);
    const int t = threadIdx.x, lane = t & 31, wid = t >> 5;
    const int wm = wid & 3, wn = wid >> 2;

    const int row0 = blockIdx.x * 64;          // DST==0
    const int kk   = blockIdx.x >> 3;          // DST==1
    const int j0   = (blockIdx.x & 7) * 64;    // DST==1

    auto apos = [&](int row) -> size_t {
        if (DST == 0) return (size_t)(row0 + row);
        else          return (size_t)(j0 + row) * NRES + kk;
    };

    const __nv_bfloat16* __restrict__ wph = g_Wth + WP * (DCH*DCH);
    const __nv_bfloat16* __restrict__ wpl = g_Wtl + WP * (DCH*DCH);
    const __nv_bfloat16* __restrict__ wgh = g_Wth + WG * (DCH*DCH);

    float accP[8][4], accG[8][4];
#pragma unroll
    for (int nt = 0; nt < 8; nt++)
#pragma unroll
        for (int c = 0; c < 4; c++) { accP[nt][c] = 0.f; accG[nt][c] = 0.f; }

    auto fill = [&](int s) {
        char* base = smem + (s & 1) * PJ_STAGE_D;
#pragma unroll
        for (int q = 0; q < 2; q++) {           // A: Xh, Xl
            int c = t + q * 256;
            int hl = c >> 8, row = (c >> 2) & 63, col = c & 3;
            const __nv_bfloat16* src = hl ? g_Xl : g_Xh;
            cp16(base + hl * PJ_A_T + row * PJ_RS + col * 16,
                 src + apos(row) * DCH + s * 32 + col * 8);
        }
        const __nv_bfloat16* wsrc[3] = {wph, wpl, wgh};
#pragma unroll
        for (int q = 0; q < 6; q++) {           // B: ph, pl, gh
            int c = t + q * 256;
            int m = c >> 9, n = (c >> 2) & 127, col = c & 3;
            cp16(base + 2 * PJ_A_T + m * PJ_B_T + n * PJ_RS + col * 16,
                 wsrc[m] + n * DCH + s * 32 + col * 8);
        }
    };

    fill(0); asm volatile("cp.async.commit_group;");
    fill(1); asm volatile("cp.async.commit_group;");

    const uint32_t aOff = (uint32_t)((wm * 16 + (lane & 15)) * PJ_RS + ((lane >> 4) << 4));
    const uint32_t bOff = (uint32_t)((wn * 64 + (lane & 15)) * PJ_RS + ((lane >> 4) << 4));

    for (int s = 0; s < 4; s++) {
        asm volatile("cp.async.wait_group 1;");
        __syncthreads();
        const uint32_t sb = sbase + (s & 1) * PJ_STAGE_D;
#pragma unroll
        for (int kh = 0; kh < 2; kh++) {
            uint32_t aH[4], aL[4];
            ldsm_x4(aH, sb + aOff + kh * 32);
            ldsm_x4(aL, sb + PJ_A_T + aOff + kh * 32);
#pragma unroll
            for (int ntp = 0; ntp < 4; ntp++) {
                const uint32_t bo = bOff + ntp * 16 * PJ_RS + kh * 32;
                uint32_t pH[4], pL[4], gH[4];
                ldsm_x4(pH, sb + 2*PJ_A_T + bo);
                ldsm_x4(pL, sb + 2*PJ_A_T + PJ_B_T + bo);
                ldsm_x4(gH, sb + 2*PJ_A_T + 2*PJ_B_T + bo);
                mma3(accP[2*ntp  ], aH, aL, pH[0], pH[2], pL[0], pL[2]);
                mma3(accP[2*ntp+1], aH, aL, pH[1], pH[3], pL[1], pL[3]);
                mma1(accG[2*ntp  ], aH, gH[0], gH[2]);
                mma1(accG[2*ntp+1], aH, gH[1], gH[3]);
            }
        }
        __syncthreads();
        if (s + 2 < 4) fill(s + 2);
        asm volatile("cp.async.commit_group;");
    }

    // Epilogue: gated value -> smem fp32 [64][129] -> bf16 hi/lo, d-major
    float* sP = reinterpret_cast<float*>(smem);
    const int g  = lane >> 2;
    const int kc = (lane & 3) * 2;
    const int ra = wm * 16 + g, rb = ra + 8;
    const float ma = mask[apos(ra)];
    const float mb = mask[apos(rb)];
#pragma unroll
    for (int nt = 0; nt < 8; nt++) {
        const int col = wn * 64 + nt * 8 + kc;
        const float bp0 = bp[col], bp1 = bp[col + 1];
        const float bg0 = bg[col], bg1 = bg[col + 1];
        sP[ra * 129 + col    ] = (accP[nt][0] + bp0) * fsig(accG[nt][0] + bg0) * ma;
        sP[ra * 129 + col + 1] = (accP[nt][1] + bp1) * fsig(accG[nt][1] + bg1) * ma;
        sP[rb * 129 + col    ] = (accP[nt][2] + bp0) * fsig(accG[nt][2] + bg0) * mb;
        sP[rb * 129 + col + 1] = (accP[nt][3] + bp1) * fsig(accG[nt][3] + bg1) * mb;
    }
    __syncthreads();
    const int dch = t >> 1, h = (t & 1) * 32;
    uint32_t wh[16], wl[16];
#pragma unroll
    for (int q = 0; q < 16; q++) {
        __nv_bfloat16 h0, l0, h1, l1;
        bsplit(sP[(h + 2*q    ) * 129 + dch], h0, l0);
        bsplit(sP[(h + 2*q + 1) * 129 + dch], h1, l1);
        wh[q] = pack2(h0, h1);
        wl[q] = pack2(l0, l1);
    }
    size_t ob;
    if (DST == 0) ob = (size_t)dch * NPOS + row0 + h;
    else          ob = (size_t)dch * NPOS + (size_t)kk * NRES + j0 + h;
    __nv_bfloat16* __restrict__ dH = DST ? g_Rh : g_Lh;
    __nv_bfloat16* __restrict__ dL = DST ? g_Rl : g_Ll;
#pragma unroll
    for (int q = 0; q < 4; q++) {
        *reinterpret_cast<uint4*>(&dH[ob + q * 8]) =
            make_uint4(wh[q*4], wh[q*4+1], wh[q*4+2], wh[q*4+3]);
        *reinterpret_cast<uint4*>(&dL[ob + q * 8]) =
            make_uint4(wl[q*4], wl[q*4+1], wl[q*4+2], wl[q*4+3]);
    }
}

// gate (1-product) -> g_gate stored [d][pos] (transposed epilogue).
template<int WIDX>
__global__ __launch_bounds__(256, 3) void proj_gate1_mma(
    const float* __restrict__ bias)
{
    extern __shared__ char smem[];
    const uint32_t sbase = (uint32_t)__cvta_generic_to_shared(smem);
    const int t = threadIdx.x, lane = t & 31, wid = t >> 5;
    const int wm = wid & 3, wn = wid >> 2;
    const int row0 = blockIdx.x * 64;

    const __nv_bfloat16* __restrict__ wh = g_Wth + WIDX * (DCH*DCH);

    float acc[8][4];
#pragma unroll
    for (int nt = 0; nt < 8; nt++)
#pragma unroll
        for (int c = 0; c < 4; c++) acc[nt][c] = 0.f;

    auto fill = [&](int s) {
        char* base = smem + (s & 1) * PJ_STAGE_S1;
        {   // A: Xh only
            int row = t >> 2, col = t & 3;
            cp16(base + row * PJ_RS + col * 16,
                 g_Xh + (size_t)(row0 + row) * DCH + s * 32 + col * 8);
        }
#pragma unroll
        for (int q = 0; q < 2; q++) {   // B: Wh only
            int c = t + q * 256;
            int n = (c >> 2) & 127, col = c & 3;
            cp16(base + PJ_A_T + n * PJ_RS + col * 16,
                 wh + n * DCH + s * 32 + col * 8);
        }
    };

    fill(0); asm volatile("cp.async.commit_group;");
    fill(1); asm volatile("cp.async.commit_group;");

    const uint32_t aOff = (uint32_t)((wm * 16 + (lane & 15)) * PJ_RS + ((lane >> 4) << 4));
    const uint32_t bOff = (uint32_t)((wn * 64 + (lane & 15)) * PJ_RS + ((lane >> 4) << 4));

    for (int s = 0; s < 4; s++) {
        asm volatile("cp.async.wait_group 1;");
        __syncthreads();
        const uint32_t sb = sbase + (s & 1) * PJ_STAGE_S1;
#pragma unroll
        for (int kh = 0; kh < 2; kh++) {
            uint32_t aH[4];
            ldsm_x4(aH, sb + aOff + kh * 32);
#pragma unroll
            for (int ntp = 0; ntp < 4; ntp++) {
                const uint32_t bo = bOff + ntp * 16 * PJ_RS + kh * 32;
                uint32_t bH[4];
                ldsm_x4(bH, sb + PJ_A_T + bo);
                mma1(acc[2*ntp  ], aH, bH[0], bH[2]);
                mma1(acc[2*ntp+1], aH, bH[1], bH[3]);
            }
        }
        __syncthreads();
        if (s + 2 < 4) fill(s + 2);
        asm volatile("cp.async.commit_group;");
    }

    // Epilogue: sigmoid -> smem [64][129] -> transpose -> g_gate[d][pos]
    float* sP = reinterpret_cast<float*>(smem);
    const int g  = lane >> 2;
    const int kc = (lane & 3) * 2;
    const int ra = wm * 16 + g, rb = ra + 8;   // tile-local rows
#pragma unroll
    for (int nt = 0; nt < 8; nt++) {
        const int col = wn * 64 + nt * 8 + kc;
        const float b0 = bias[col], b1 = bias[col + 1];
        sP[ra * 129 + col    ] = fsig(acc[nt][0] + b0);
        sP[ra * 129 + col + 1] = fsig(acc[nt][1] + b1);
        sP[rb * 129 + col    ] = fsig(acc[nt][2] + b0);
        sP[rb * 129 + col + 1] = fsig(acc[nt][3] + b1);
    }
    __syncthreads();
    const int dch = t >> 1, h = (t & 1) * 32;
    float* __restrict__ dstG = g_gate + (size_t)dch * NPOS + row0 + h;
#pragma unroll
    for (int q = 0; q < 8; q++) {
        float4 v;
        v.x = sP[(h + 4*q    ) * 129 + dch];
        v.y = sP[(h + 4*q + 1) * 129 + dch];
        v.z = sP[(h + 4*q + 2) * 129 + dch];
        v.w = sP[(h + 4*q + 3) * 129 + dch];
        *reinterpret_cast<float4*>(&dstG[4*q]) = v;
    }
}

// ---------------------------------------------------------------------------
// K4: einsum via mma.sync (3-stage ring, proven). Epilogue now applies the
// gate ([d][pos], coalesced), bsplits, writes PRE hi/lo to g_Xh/g_Xl [d][pos].
// ---------------------------------------------------------------------------
#define EM_RS     80
#define EM_A_T    (128 * EM_RS)
#define EM_B_T    (64 * EM_RS)
#define EM_STAGE  (2 * EM_A_T + 2 * EM_B_T)
#define EM_SMEM   (3 * EM_STAGE)

__global__ __launch_bounds__(256, 2) void einsum_mma_kernel()
{
    extern __shared__ char smem[];
    const uint32_t sbase = (uint32_t)__cvta_generic_to_shared(smem);
    const int t    = threadIdx.x;
    const int lane = t & 31;
    const int wid  = t >> 5;
    const int wm   = wid & 3;
    const int wn   = wid >> 2;

    const int bid = blockIdx.x;
    const int d   = bid >> 5;
    const int i0  = ((bid >> 3) & 3) * 128;
    const int k0  = (bid & 7) * 64;

    const __nv_bfloat16* __restrict__ pLh = g_Lh + (size_t)d * NPOS + (size_t)i0 * NRES;
    const __nv_bfloat16* __restrict__ pLl = g_Ll + (size_t)d * NPOS + (size_t)i0 * NRES;
    const __nv_bfloat16* __restrict__ pRh = g_Rh + (size_t)d * NPOS + (size_t)k0 * NRES;
    const __nv_bfloat16* __restrict__ pRl = g_Rl + (size_t)d * NPOS + (size_t)k0 * NRES;

    float acc[2][4][4];
#pragma unroll
    for (int mt = 0; mt < 2; mt++)
#pragma unroll
        for (int nt = 0; nt < 4; nt++)
#pragma unroll
            for (int c = 0; c < 4; c++) acc[mt][nt][c] = 0.0f;

    auto fill = [&](int s) {
        const int buf = s % 3;
        char* base = smem + buf * EM_STAGE;
        const int j0s = s * 32;
        {
            int c0 = t, c1 = t + 256;
            int r0 = c0 >> 2, r1 = c1 >> 2, col0 = c0 & 3, col1 = c1 & 3;
            cp16(base + r0 * EM_RS + col0 * 16,
                 pLh + (size_t)r0 * NRES + j0s + col0 * 8);
            cp16(base + r1 * EM_RS + col1 * 16,
                 pLh + (size_t)r1 * NRES + j0s + col1 * 8);
            cp16(base + EM_A_T + r0 * EM_RS + col0 * 16,
                 pLl + (size_t)r0 * NRES + j0s + col0 * 8);
            cp16(base + EM_A_T + r1 * EM_RS + col1 * 16,
                 pLl + (size_t)r1 * NRES + j0s + col1 * 8);
        }
        {
            int r = t >> 2, col = t & 3;
            cp16(base + 2 * EM_A_T + r * EM_RS + col * 16,
                 pRh + (size_t)r * NRES + j0s + col * 8);
            cp16(base + 2 * EM_A_T + EM_B_T + r * EM_RS + col * 16,
                 pRl + (size_t)r * NRES + j0s + col * 8);
        }
    };

    fill(0); asm volatile("cp.async.commit_group;");
    fill(1); asm volatile("cp.async.commit_group;");

    const uint32_t aOff = (uint32_t)((wm * 32 + ((lane >> 3) & 1) * 8 + (lane & 7)) * EM_RS
                                     + ((lane >> 4) << 4));
    const uint32_t bOff = (uint32_t)((wn * 32 + (lane & 7)) * EM_RS
                                     + (((lane >> 3) & 1) << 4));

    for (int s = 0; s < 16; s++) {
        asm volatile("cp.async.wait_group 1;");
        __syncthreads();
        if (s + 2 < 16) fill(s + 2);
        asm volatile("cp.async.commit_group;");

        const uint32_t sb  = sbase + (s % 3) * EM_STAGE;
        const uint32_t aHb = sb, aLb = sb + EM_A_T;
        const uint32_t bHb = sb + 2 * EM_A_T, bLb = bHb + EM_B_T;

#pragma unroll
        for (int kh = 0; kh < 2; kh++) {
            const uint32_t kb = kh * 32;
            uint32_t aH[2][4], aL[2][4];
            ldsm_x4(aH[0], aHb + aOff + kb);
            ldsm_x4(aH[1], aHb + aOff + 16 * EM_RS + kb);
            ldsm_x4(aL[0], aLb + aOff + kb);
            ldsm_x4(aL[1], aLb + aOff + 16 * EM_RS + kb);
#pragma unroll
            for (int nt = 0; nt < 4; nt++) {
                uint32_t bH[2], bL[2];
                ldsm_x2(bH, bHb + bOff + nt * 8 * EM_RS + kb);
                ldsm_x2(bL, bLb + bOff + nt * 8 * EM_RS + kb);
#pragma unroll
                for (int mt = 0; mt < 2; mt++) {
                    mma16816(acc[mt][nt], aH[mt], bH);
                    mma16816(acc[mt][nt], aH[mt], bL);
                    mma16816(acc[mt][nt], aL[mt], bH);
                }
            }
        }
    }

    // Epilogue: gate (coalesced, [d][pos]), bsplit, write PRE hi/lo [d][pos].
    const float* __restrict__ pG = g_gate + (size_t)d * NPOS;
    __nv_bfloat16* __restrict__ pH = g_Xh + (size_t)d * NPOS;
    __nv_bfloat16* __restrict__ pL = g_Xl + (size_t)d * NPOS;
    const int g  = lane >> 2;
    const int kc = (lane & 3) * 2;
#pragma unroll
    for (int mt = 0; mt < 2; mt++) {
#pragma unroll
        for (int nt = 0; nt < 4; nt++) {
            const int i = i0 + wm * 32 + mt * 16 + g;
            const int k = k0 + wn * 32 + nt * 8 + kc;
            const float2 ga = *reinterpret_cast<const float2*>(&pG[(size_t)i * NRES + k]);
            const float2 gb = *reinterpret_cast<const float2*>(&pG[(size_t)(i + 8) * NRES + k]);
            float xa = acc[mt][nt][0] * ga.x, ya = acc[mt][nt][1] * ga.y;
            float xb = acc[mt][nt][2] * gb.x, yb = acc[mt][nt][3] * gb.y;
            __nv_bfloat16 h0,l0,h1,l1;
            bsplit(xa, h0, l0); bsplit(ya, h1, l1);
            *reinterpret_cast<uint32_t*>(&pH[(size_t)i * NRES + k]) = pack2(h0, h1);
            *reinterpret_cast<uint32_t*>(&pL[(size_t)i * NRES + k]) = pack2(l0, l1);
            bsplit(xb, h0, l0); bsplit(yb, h1, l1);
            *reinterpret_cast<uint32_t*>(&pH[(size_t)(i + 8) * NRES + k]) = pack2(h0, h1);
            *reinterpret_cast<uint32_t*>(&pL[(size_t)(i + 8) * NRES + k]) = pack2(l0, l1);
        }
    }
}

// ---------------------------------------------------------------------------
// K5: out = PRE@Wo + b, PRE hi/lo in [d][pos] (g_Xh/g_Xl), A via ldmatrix.trans.
// M tile 64 pos, K=128 d in 4 stages of 32. 8 warps = 4M x 2N.
// ---------------------------------------------------------------------------
#define PO_RS_A   144                          // 32 d-rows x (64 pos * 2B = 128B) + pad
#define PO_A_SLAB (32 * PO_RS_A)               // 4608
#define PO_B_SLAB (128 * PJ_RS)                // 10240
#define PO_STAGE  (2*PO_A_SLAB + 2*PO_B_SLAB)  // 29696
#define PO_SMEM   (2 * PO_STAGE)               // 59392

template<int WIDX>
__global__ __launch_bounds__(256, 2) void proj_out_trans(
    const float* __restrict__ bias, float* __restrict__ dst)
{
    extern __shared__ char smem[];
    const uint32_t sbase = (uint32_t)__cvta_generic_to_shared(smem);
    const int t = threadIdx.x, lane = t & 31, wid = t >> 5;
    const int wm = wid & 3, wn = wid >> 2;
    const int row0 = blockIdx.x * 64;            // pos base

    const __nv_bfloat16* __restrict__ wh = g_Wth + WIDX * (DCH*DCH);
    const __nv_bfloat16* __restrict__ wl = g_Wtl + WIDX * (DCH*DCH);

    float acc[8][4];
#pragma unroll
    for (int nt = 0; nt < 8; nt++)
#pragma unroll
        for (int c = 0; c < 4; c++) acc[nt][c] = 0.f;

    auto fill = [&](int s) {
        char* base = smem + (s & 1) * PO_STAGE;
#pragma unroll
        for (int q = 0; q < 2; q++) {    // A: PRE hi, lo — [d-rows][pos cols]
            const __nv_bfloat16* src = q ? g_Xl : g_Xh;
            int row = t >> 3, col = t & 7;     // 32 rows x 8 x 16B
            cp16(base + q * PO_A_SLAB + row * PO_RS_A + col * 16,
                 src + (size_t)(s * 32 + row) * NPOS + row0 + col * 8);
        }
        const __nv_bfloat16* wsrc[2] = {wh, wl};
#pragma unroll
        for (int q = 0; q < 4; q++) {    // B: Wo hi, lo
            int c = t + q * 256;
            int m = c >> 9, n = (c >> 2) & 127, col = c & 3;
            cp16(base + 2 * PO_A_SLAB + m * PO_B_SLAB + n * PJ_RS + col * 16,
                 wsrc[m] + n * DCH + s * 32 + col * 8);
        }
    };

    fill(0); asm volatile("cp.async.commit_group;");
    fill(1); asm volatile("cp.async.commit_group;");

    // trans-A lane mapping: lane groups of 8 load 8x8 tiles
    //   tile0 (lanes 0-7):  d rows 0-7,  pos cols wm*16+0..7   -> a[0] (m0,k0)
    //   tile1 (lanes 8-15): d rows 0-7,  pos cols wm*16+8..15  -> a[1] (m8,k0)
    //   tile2 (lanes16-23): d rows 8-15, pos cols wm*16+0..7   -> a[2] (m0,k8)
    //   tile3 (lanes24-31): d rows 8-15, pos cols wm*16+8..15  -> a[3] (m8,k8)
    const uint32_t aOffT = (uint32_t)(((lane & 7) + ((lane >> 4) << 3)) * PO_RS_A
                                      + wm * 32 + ((lane >> 3) & 1) * 16);
    const uint32_t bOff  = (uint32_t)((wn * 64 + (lane & 15)) * PJ_RS + ((lane >> 4) << 4));

    for (int s = 0; s < 4; s++) {
        asm volatile("cp.async.wait_group 1;");
        __syncthreads();
        const uint32_t sb = sbase + (s & 1) * PO_STAGE;
#pragma unroll
        for (int kh = 0; kh < 2; kh++) {
            uint32_t aH[4], aL[4];
            ldsm_x4t(aH, sb + aOffT + kh * 16 * PO_RS_A);
            ldsm_x4t(aL, sb + PO_A_SLAB + aOffT + kh * 16 * PO_RS_A);
#pragma unroll
            for (int ntp = 0; ntp < 4; ntp++) {
                const uint32_t bo = bOff + ntp * 16 * PJ_RS + kh * 32;
                uint32_t bH[4], bL[4];
                ldsm_x4(bH, sb + 2*PO_A_SLAB + bo);
                ldsm_x4(bL, sb + 2*PO_A_SLAB + PO_B_SLAB + bo);
                mma3(acc[2*ntp  ], aH, aL, bH[0], bH[2], bL[0], bL[2]);
                mma3(acc[2*ntp+1], aH, aL, bH[1], bH[3], bL[1], bL[3]);
            }
        }
        __syncthreads();
        if (s + 2 < 4) fill(s + 2);
        asm volatile("cp.async.commit_group;");
    }

    const int g  = lane >> 2;
    const int kc = (lane & 3) * 2;
    const int ra = row0 + wm * 16 + g, rb = ra + 8;
#pragma unroll
    for (int nt = 0; nt < 8; nt++) {
        const int col = wn * 64 + nt * 8 + kc;
        const float b0 = bias[col], b1 = bias[col + 1];
        float2 oa, ob;
        oa.x = acc[nt][0] + b0; oa.y = acc[nt][1] + b1;
        ob.x = acc[nt][2] + b0; ob.y = acc[nt][3] + b1;
        *reinterpret_cast<float2*>(&dst[(size_t)ra * DCH + col]) = oa;
        *reinterpret_cast<float2*>(&dst[(size_t)rb * DCH + col]) = ob;
    }
}

// ---------------------------------------------------------------------------
extern "C" void kernel_launch(void* const* d_in, const int* in_sizes, int n_in,
                              void* d_out, int out_size)
{
    (void)in_sizes; (void)n_in; (void)out_size;
    const float* pair = (const float*)d_in[0];
    const float* mask = (const float*)d_in[1];
    const float* ln_g = (const float*)d_in[2];
    const float* ln_b = (const float*)d_in[3];
    const float* w_lp = (const float*)d_in[4];
    const float* b_lp = (const float*)d_in[5];
    const float* w_lg = (const float*)d_in[6];
    const float* b_lg = (const float*)d_in[7];
    const float* w_rp = (const float*)d_in[8];
    const float* b_rp = (const float*)d_in[9];
    const float* w_rg = (const float*)d_in[10];
    const float* b_rg = (const float*)d_in[11];
    const float* w_g  = (const float*)d_in[12];
    const float* b_g  = (const float*)d_in[13];
    const float* w_o  = (const float*)d_in[14];
    const float* b_o  = (const float*)d_in[15];
    float* out = (float*)d_out;

    cudaFuncSetAttribute(einsum_mma_kernel,
                         cudaFuncAttributeMaxDynamicSharedMemorySize, EM_SMEM);
    cudaFuncSetAttribute(proj_dual_mma<0,1,0>,
                         cudaFuncAttributeMaxDynamicSharedMemorySize, PJ_SMEM_D);
    cudaFuncSetAttribute(proj_dual_mma<2,3,1>,
                         cudaFuncAttributeMaxDynamicSharedMemorySize, PJ_SMEM_D);
    cudaFuncSetAttribute(proj_gate1_mma<4>,
                         cudaFuncAttributeMaxDynamicSharedMemorySize, PJ_SMEM_S1);
    cudaFuncSetAttribute(proj_out_trans<5>,
                         cudaFuncAttributeMaxDynamicSharedMemorySize, PO_SMEM);

    prep_weights<<<6, 256>>>(w_lp, w_lg, w_rp, w_rg, w_g, w_o);
    ln_split_kernel<<<NPOS / 8, 256>>>(pair, ln_g, ln_b);
    proj_dual_mma<0,1,0><<<NPOS / 64, 256, PJ_SMEM_D>>>(b_lp, b_lg, mask);
    proj_dual_mma<2,3,1><<<NPOS / 64, 256, PJ_SMEM_D>>>(b_rp, b_rg, mask);
    proj_gate1_mma<4><<<NPOS / 64, 256, PJ_SMEM_S1>>>(b_g);
    einsum_mma_kernel<<<4096, 256, EM_SMEM>>>();
    proj_out_trans<5><<<NPOS / 64, 256, PO_SMEM>>>(b_o, out);
}

// round 17
// speedup vs baseline: 1.0744x; 1.0744x over previous
#include <cuda_runtime.h>
#include <cuda_bf16.h>
#include <cstdint>

#define NRES 512
#define DCH  128
#define NPOS (NRES*NRES)

// Scratch (device globals — no runtime allocation allowed)
__device__ float g_gate [(size_t)NPOS * DCH];        // gate, [pos][d]
__device__ float g_pret [(size_t)NPOS * DCH];        // einsum out, [d][pos]
__device__ __nv_bfloat16 g_Xh[(size_t)NPOS * DCH];   // LN(x) split, [pos][d]
__device__ __nv_bfloat16 g_Xl[(size_t)NPOS * DCH];
__device__ __nv_bfloat16 g_Lh[(size_t)DCH * NPOS];   // left  [d][i][j]
__device__ __nv_bfloat16 g_Ll[(size_t)DCH * NPOS];
__device__ __nv_bfloat16 g_Rh[(size_t)DCH * NPOS];   // right [d][k][j]
__device__ __nv_bfloat16 g_Rl[(size_t)DCH * NPOS];
__device__ __nv_bfloat16 g_Wth[6 * DCH * DCH];       // W^T hi, [widx][n][k]
__device__ __nv_bfloat16 g_Wtl[6 * DCH * DCH];       // W^T lo

__device__ __forceinline__ float fsig(float x) { return 1.0f / (1.0f + __expf(-x)); }

__device__ __forceinline__ void cp16(void* s, const void* g) {
    unsigned sa = (unsigned)__cvta_generic_to_shared(s);
    asm volatile("cp.async.cg.shared.global [%0], [%1], 16;" :: "r"(sa), "l"(g));
}

// ---- mma.sync / ldmatrix (sm_80-class PTX: compiles on plain sm_103) ------
__device__ __forceinline__ void ldsm_x4(uint32_t* r, uint32_t addr) {
    asm volatile("ldmatrix.sync.aligned.m8n8.x4.shared.b16 {%0,%1,%2,%3}, [%4];"
        : "=r"(r[0]), "=r"(r[1]), "=r"(r[2]), "=r"(r[3]) : "r"(addr));
}
__device__ __forceinline__ void ldsm_x2(uint32_t* r, uint32_t addr) {
    asm volatile("ldmatrix.sync.aligned.m8n8.x2.shared.b16 {%0,%1}, [%2];"
        : "=r"(r[0]), "=r"(r[1]) : "r"(addr));
}
__device__ __forceinline__ void mma16816(float* c, const uint32_t* a, const uint32_t* b) {
    asm volatile("mma.sync.aligned.m16n8k16.row.col.f32.bf16.bf16.f32 "
        "{%0,%1,%2,%3}, {%4,%5,%6,%7}, {%8,%9}, {%0,%1,%2,%3};"
        : "+f"(c[0]), "+f"(c[1]), "+f"(c[2]), "+f"(c[3])
        : "r"(a[0]), "r"(a[1]), "r"(a[2]), "r"(a[3]), "r"(b[0]), "r"(b[1]));
}
// C += Ah*Bh + Ah*Bl + Al*Bh   (bf16 hi/lo split product)
__device__ __forceinline__ void mma3(float* c, const uint32_t* aH, const uint32_t* aL,
                                     uint32_t bh0, uint32_t bh1,
                                     uint32_t bl0, uint32_t bl1) {
    uint32_t b[2];
    b[0] = bh0; b[1] = bh1; mma16816(c, aH, b);
    b[0] = bl0; b[1] = bl1; mma16816(c, aH, b);
    b[0] = bh0; b[1] = bh1; mma16816(c, aL, b);
}
// C += Ah*Bh only (single product; sigmoid-gate logits)
__device__ __forceinline__ void mma1(float* c, const uint32_t* aH,
                                     uint32_t b0, uint32_t b1) {
    uint32_t b[2];
    b[0] = b0; b[1] = b1; mma16816(c, aH, b);
}

__device__ __forceinline__ void bsplit(float v, __nv_bfloat16& h, __nv_bfloat16& l) {
    h = __float2bfloat16(v);
    l = __float2bfloat16(v - __bfloat162float(h));
}
__device__ __forceinline__ uint32_t pack2(__nv_bfloat16 a, __nv_bfloat16 b) {
    __nv_bfloat162 p(a, b);
    return *reinterpret_cast<uint32_t*>(&p);
}

// ---------------------------------------------------------------------------
// K0: weight prep — W[k][n] -> Wt_h/Wt_l[n][k] bf16. One block per matrix.
// ---------------------------------------------------------------------------
__global__ void prep_weights(const float* w0, const float* w1, const float* w2,
                             const float* w3, const float* w4, const float* w5)
{
    const float* srcs[6] = {w0, w1, w2, w3, w4, w5};
    const float* src = srcs[blockIdx.x];
    const int base = blockIdx.x * DCH * DCH;
    for (int idx = threadIdx.x; idx < DCH * DCH; idx += blockDim.x) {
        int k = idx >> 7, n = idx & 127;
        __nv_bfloat16 h, l;
        bsplit(src[idx], h, l);
        g_Wth[base + n * DCH + k] = h;
        g_Wtl[base + n * DCH + k] = l;
    }
}

// ---------------------------------------------------------------------------
// K1: LayerNorm over D=128 -> Xh/Xl bf16 [pos][d].
// ---------------------------------------------------------------------------
__global__ void ln_split_kernel(const float* __restrict__ pair,
                                const float* __restrict__ lng,
                                const float* __restrict__ lnb)
{
    const int lane = threadIdx.x & 31;
    const int row  = blockIdx.x * 8 + (threadIdx.x >> 5);
    const float4 v = reinterpret_cast<const float4*>(pair)[(size_t)row * 32 + lane];
    float s = v.x + v.y + v.z + v.w;
    float q = v.x*v.x + v.y*v.y + v.z*v.z + v.w*v.w;
#pragma unroll
    for (int o = 16; o > 0; o >>= 1) {
        s += __shfl_xor_sync(0xffffffffu, s, o);
        q += __shfl_xor_sync(0xffffffffu, q, o);
    }
    const float mean = s * (1.0f / 128.0f);
    const float var  = q * (1.0f / 128.0f) - mean * mean;
    const float rs   = rsqrtf(var + 1e-5f);
    const float4 g4 = reinterpret_cast<const float4*>(lng)[lane];
    const float4 b4 = reinterpret_cast<const float4*>(lnb)[lane];
    float o0 = (v.x - mean) * rs * g4.x + b4.x;
    float o1 = (v.y - mean) * rs * g4.y + b4.y;
    float o2 = (v.z - mean) * rs * g4.z + b4.z;
    float o3 = (v.w - mean) * rs * g4.w + b4.w;
    __nv_bfloat16 h0,l0,h1,l1,h2,l2,h3,l3;
    bsplit(o0,h0,l0); bsplit(o1,h1,l1); bsplit(o2,h2,l2); bsplit(o3,h3,l3);
    uint2 hv = make_uint2(pack2(h0,h1), pack2(h2,h3));
    uint2 lv = make_uint2(pack2(l0,l1), pack2(l2,l3));
    *reinterpret_cast<uint2*>(&g_Xh[(size_t)row * DCH + lane * 4]) = hv;
    *reinterpret_cast<uint2*>(&g_Xl[(size_t)row * DCH + lane * 4]) = lv;
}

// ---------------------------------------------------------------------------
// Projection GEMMs on mma.sync. M tile 64 x N 128, K=128 in 4 stages of 32.
// 8 warps = 4M x 2N, warp = 16 rows x 64 cols.
// ---------------------------------------------------------------------------
#define PJ_RS      80
#define PJ_A_T     (64 * PJ_RS)               // 5120
#define PJ_B_T     (128 * PJ_RS)              // 10240
#define PJ_STAGE_D (2*PJ_A_T + 3*PJ_B_T)      // 40960 (P hi/lo + G hi only)
#define PJ_SMEM_D  (2 * PJ_STAGE_D)           // 81920
#define PJ_STAGE_S1 (PJ_A_T + PJ_B_T)         // 15360
#define PJ_SMEM_S1  (2 * PJ_STAGE_S1)         // 30720

// dual: v = (X@Wp + bp) * sigmoid(X@Wg + bg) * mask, hi/lo split + transpose
// (R13, proven). DST 0 -> g_Lh/g_Ll [d][i][j]; DST 1 -> g_Rh/g_Rl [d][k][j].
template<int WP, int WG, int DST>
__global__ __launch_bounds__(256, 2) void proj_dual_mma(
    const float* __restrict__ bp, const float* __restrict__ bg,
    const float* __restrict__ mask)
{
    extern __shared__ char smem[];
    const uint32_t sbase = (uint32_t)__cvta_generic_to_shared(smem);
    const int t = threadIdx.x, lane = t & 31, wid = t >> 5;
    const int wm = wid & 3, wn = wid >> 2;

    const int row0 = blockIdx.x * 64;          // DST==0
    const int kk   = blockIdx.x >> 3;          // DST==1
    const int j0   = (blockIdx.x & 7) * 64;    // DST==1

    auto apos = [&](int row) -> size_t {
        if (DST == 0) return (size_t)(row0 + row);
        else          return (size_t)(j0 + row) * NRES + kk;
    };

    const __nv_bfloat16* __restrict__ wph = g_Wth + WP * (DCH*DCH);
    const __nv_bfloat16* __restrict__ wpl = g_Wtl + WP * (DCH*DCH);
    const __nv_bfloat16* __restrict__ wgh = g_Wth + WG * (DCH*DCH);

    float accP[8][4], accG[8][4];
#pragma unroll
    for (int nt = 0; nt < 8; nt++)
#pragma unroll
        for (int c = 0; c < 4; c++) { accP[nt][c] = 0.f; accG[nt][c] = 0.f; }

    auto fill = [&](int s) {
        char* base = smem + (s & 1) * PJ_STAGE_D;
#pragma unroll
        for (int q = 0; q < 2; q++) {           // A: Xh, Xl
            int c = t + q * 256;
            int hl = c >> 8, row = (c >> 2) & 63, col = c & 3;
            const __nv_bfloat16* src = hl ? g_Xl : g_Xh;
            cp16(base + hl * PJ_A_T + row * PJ_RS + col * 16,
                 src + apos(row) * DCH + s * 32 + col * 8);
        }
        const __nv_bfloat16* wsrc[3] = {wph, wpl, wgh};
#pragma unroll
        for (int q = 0; q < 6; q++) {           // B: ph, pl, gh
            int c = t + q * 256;
            int m = c >> 9, n = (c >> 2) & 127, col = c & 3;
            cp16(base + 2 * PJ_A_T + m * PJ_B_T + n * PJ_RS + col * 16,
                 wsrc[m] + n * DCH + s * 32 + col * 8);
        }
    };

    fill(0); asm volatile("cp.async.commit_group;");
    fill(1); asm volatile("cp.async.commit_group;");

    const uint32_t aOff = (uint32_t)((wm * 16 + (lane & 15)) * PJ_RS + ((lane >> 4) << 4));
    const uint32_t bOff = (uint32_t)((wn * 64 + (lane & 15)) * PJ_RS + ((lane >> 4) << 4));

    for (int s = 0; s < 4; s++) {
        asm volatile("cp.async.wait_group 1;");
        __syncthreads();
        const uint32_t sb = sbase + (s & 1) * PJ_STAGE_D;
#pragma unroll
        for (int kh = 0; kh < 2; kh++) {
            uint32_t aH[4], aL[4];
            ldsm_x4(aH, sb + aOff + kh * 32);
            ldsm_x4(aL, sb + PJ_A_T + aOff + kh * 32);
#pragma unroll
            for (int ntp = 0; ntp < 4; ntp++) {
                const uint32_t bo = bOff + ntp * 16 * PJ_RS + kh * 32;
                uint32_t pH[4], pL[4], gH[4];
                ldsm_x4(pH, sb + 2*PJ_A_T + bo);
                ldsm_x4(pL, sb + 2*PJ_A_T + PJ_B_T + bo);
                ldsm_x4(gH, sb + 2*PJ_A_T + 2*PJ_B_T + bo);
                mma3(accP[2*ntp  ], aH, aL, pH[0], pH[2], pL[0], pL[2]);
                mma3(accP[2*ntp+1], aH, aL, pH[1], pH[3], pL[1], pL[3]);
                mma1(accG[2*ntp  ], aH, gH[0], gH[2]);
                mma1(accG[2*ntp+1], aH, gH[1], gH[3]);
            }
        }
        __syncthreads();
        if (s + 2 < 4) fill(s + 2);
        asm volatile("cp.async.commit_group;");
    }

    // Epilogue: gated value -> smem fp32 [64][129] -> bf16 hi/lo, d-major
    float* sP = reinterpret_cast<float*>(smem);
    const int g  = lane >> 2;
    const int kc = (lane & 3) * 2;
    const int ra = wm * 16 + g, rb = ra + 8;
    const float ma = mask[apos(ra)];
    const float mb = mask[apos(rb)];
#pragma unroll
    for (int nt = 0; nt < 8; nt++) {
        const int col = wn * 64 + nt * 8 + kc;
        const float bp0 = bp[col], bp1 = bp[col + 1];
        const float bg0 = bg[col], bg1 = bg[col + 1];
        sP[ra * 129 + col    ] = (accP[nt][0] + bp0) * fsig(accG[nt][0] + bg0) * ma;
        sP[ra * 129 + col + 1] = (accP[nt][1] + bp1) * fsig(accG[nt][1] + bg1) * ma;
        sP[rb * 129 + col    ] = (accP[nt][2] + bp0) * fsig(accG[nt][2] + bg0) * mb;
        sP[rb * 129 + col + 1] = (accP[nt][3] + bp1) * fsig(accG[nt][3] + bg1) * mb;
    }
    __syncthreads();
    const int dch = t >> 1, h = (t & 1) * 32;
    uint32_t wh[16], wl[16];
#pragma unroll
    for (int q = 0; q < 16; q++) {
        __nv_bfloat16 h0, l0, h1, l1;
        bsplit(sP[(h + 2*q    ) * 129 + dch], h0, l0);
        bsplit(sP[(h + 2*q + 1) * 129 + dch], h1, l1);
        wh[q] = pack2(h0, h1);
        wl[q] = pack2(l0, l1);
    }
    size_t ob;
    if (DST == 0) ob = (size_t)dch * NPOS + row0 + h;
    else          ob = (size_t)dch * NPOS + (size_t)kk * NRES + j0 + h;
    __nv_bfloat16* __restrict__ dH = DST ? g_Rh : g_Lh;
    __nv_bfloat16* __restrict__ dL = DST ? g_Rl : g_Ll;
#pragma unroll
    for (int q = 0; q < 4; q++) {
        *reinterpret_cast<uint4*>(&dH[ob + q * 8]) =
            make_uint4(wh[q*4], wh[q*4+1], wh[q*4+2], wh[q*4+3]);
        *reinterpret_cast<uint4*>(&dL[ob + q * 8]) =
            make_uint4(wl[q*4], wl[q*4+1], wl[q*4+2], wl[q*4+3]);
    }
}

// gate (1-product): g_gate = sigmoid(Xh@Wh + b), [pos][d]  (R13, proven)
template<int WIDX>
__global__ __launch_bounds__(256, 3) void proj_gate1_mma(
    const float* __restrict__ bias)
{
    extern __shared__ char smem[];
    const uint32_t sbase = (uint32_t)__cvta_generic_to_shared(smem);
    const int t = threadIdx.x, lane = t & 31, wid = t >> 5;
    const int wm = wid & 3, wn = wid >> 2;
    const int row0 = blockIdx.x * 64;

    const __nv_bfloat16* __restrict__ wh = g_Wth + WIDX * (DCH*DCH);

    float acc[8][4];
#pragma unroll
    for (int nt = 0; nt < 8; nt++)
#pragma unroll
        for (int c = 0; c < 4; c++) acc[nt][c] = 0.f;

    auto fill = [&](int s) {
        char* base = smem + (s & 1) * PJ_STAGE_S1;
        {
            int row = t >> 2, col = t & 3;
            cp16(base + row * PJ_RS + col * 16,
                 g_Xh + (size_t)(row0 + row) * DCH + s * 32 + col * 8);
        }
#pragma unroll
        for (int q = 0; q < 2; q++) {
            int c = t + q * 256;
            int n = (c >> 2) & 127, col = c & 3;
            cp16(base + PJ_A_T + n * PJ_RS + col * 16,
                 wh + n * DCH + s * 32 + col * 8);
        }
    };

    fill(0); asm volatile("cp.async.commit_group;");
    fill(1); asm volatile("cp.async.commit_group;");

    const uint32_t aOff = (uint32_t)((wm * 16 + (lane & 15)) * PJ_RS + ((lane >> 4) << 4));
    const uint32_t bOff = (uint32_t)((wn * 64 + (lane & 15)) * PJ_RS + ((lane >> 4) << 4));

    for (int s = 0; s < 4; s++) {
        asm volatile("cp.async.wait_group 1;");
        __syncthreads();
        const uint32_t sb = sbase + (s & 1) * PJ_STAGE_S1;
#pragma unroll
        for (int kh = 0; kh < 2; kh++) {
            uint32_t aH[4];
            ldsm_x4(aH, sb + aOff + kh * 32);
#pragma unroll
            for (int ntp = 0; ntp < 4; ntp++) {
                const uint32_t bo = bOff + ntp * 16 * PJ_RS + kh * 32;
                uint32_t bH[4];
                ldsm_x4(bH, sb + PJ_A_T + bo);
                mma1(acc[2*ntp  ], aH, bH[0], bH[2]);
                mma1(acc[2*ntp+1], aH, bH[1], bH[3]);
            }
        }
        __syncthreads();
        if (s + 2 < 4) fill(s + 2);
        asm volatile("cp.async.commit_group;");
    }

    const int g  = lane >> 2;
    const int kc = (lane & 3) * 2;
    const int ra = row0 + wm * 16 + g, rb = ra + 8;
#pragma unroll
    for (int nt = 0; nt < 8; nt++) {
        const int col = wn * 64 + nt * 8 + kc;
        const float b0 = bias[col], b1 = bias[col + 1];
        float2 oa, ob;
        oa.x = fsig(acc[nt][0] + b0); oa.y = fsig(acc[nt][1] + b1);
        ob.x = fsig(acc[nt][2] + b0); ob.y = fsig(acc[nt][3] + b1);
        *reinterpret_cast<float2*>(&g_gate[(size_t)ra * DCH + col]) = oa;
        *reinterpret_cast<float2*>(&g_gate[(size_t)rb * DCH + col]) = ob;
    }
}

// ---------------------------------------------------------------------------
// K4: einsum via mma.sync (R13, proven — 3-stage ring, writes g_pret [d][pos]).
// ---------------------------------------------------------------------------
#define EM_RS     80
#define EM_A_T    (128 * EM_RS)
#define EM_B_T    (64 * EM_RS)
#define EM_STAGE  (2 * EM_A_T + 2 * EM_B_T)
#define EM_SMEM   (3 * EM_STAGE)

__global__ __launch_bounds__(256, 2) void einsum_mma_kernel()
{
    extern __shared__ char smem[];
    const uint32_t sbase = (uint32_t)__cvta_generic_to_shared(smem);
    const int t    = threadIdx.x;
    const int lane = t & 31;
    const int wid  = t >> 5;
    const int wm   = wid & 3;
    const int wn   = wid >> 2;

    const int bid = blockIdx.x;
    const int d   = bid >> 5;
    const int i0  = ((bid >> 3) & 3) * 128;
    const int k0  = (bid & 7) * 64;

    const __nv_bfloat16* __restrict__ pLh = g_Lh + (size_t)d * NPOS + (size_t)i0 * NRES;
    const __nv_bfloat16* __restrict__ pLl = g_Ll + (size_t)d * NPOS + (size_t)i0 * NRES;
    const __nv_bfloat16* __restrict__ pRh = g_Rh + (size_t)d * NPOS + (size_t)k0 * NRES;
    const __nv_bfloat16* __restrict__ pRl = g_Rl + (size_t)d * NPOS + (size_t)k0 * NRES;

    float acc[2][4][4];
#pragma unroll
    for (int mt = 0; mt < 2; mt++)
#pragma unroll
        for (int nt = 0; nt < 4; nt++)
#pragma unroll
            for (int c = 0; c < 4; c++) acc[mt][nt][c] = 0.0f;

    auto fill = [&](int s) {
        const int buf = s % 3;
        char* base = smem + buf * EM_STAGE;
        const int j0s = s * 32;
        {
            int c0 = t, c1 = t + 256;
            int r0 = c0 >> 2, r1 = c1 >> 2, col0 = c0 & 3, col1 = c1 & 3;
            cp16(base + r0 * EM_RS + col0 * 16,
                 pLh + (size_t)r0 * NRES + j0s + col0 * 8);
            cp16(base + r1 * EM_RS + col1 * 16,
                 pLh + (size_t)r1 * NRES + j0s + col1 * 8);
            cp16(base + EM_A_T + r0 * EM_RS + col0 * 16,
                 pLl + (size_t)r0 * NRES + j0s + col0 * 8);
            cp16(base + EM_A_T + r1 * EM_RS + col1 * 16,
                 pLl + (size_t)r1 * NRES + j0s + col1 * 8);
        }
        {
            int r = t >> 2, col = t & 3;
            cp16(base + 2 * EM_A_T + r * EM_RS + col * 16,
                 pRh + (size_t)r * NRES + j0s + col * 8);
            cp16(base + 2 * EM_A_T + EM_B_T + r * EM_RS + col * 16,
                 pRl + (size_t)r * NRES + j0s + col * 8);
        }
    };

    fill(0); asm volatile("cp.async.commit_group;");
    fill(1); asm volatile("cp.async.commit_group;");

    const uint32_t aOff = (uint32_t)((wm * 32 + ((lane >> 3) & 1) * 8 + (lane & 7)) * EM_RS
                                     + ((lane >> 4) << 4));
    const uint32_t bOff = (uint32_t)((wn * 32 + (lane & 7)) * EM_RS
                                     + (((lane >> 3) & 1) << 4));

    for (int s = 0; s < 16; s++) {
        asm volatile("cp.async.wait_group 1;");
        __syncthreads();
        if (s + 2 < 16) fill(s + 2);
        asm volatile("cp.async.commit_group;");

        const uint32_t sb  = sbase + (s % 3) * EM_STAGE;
        const uint32_t aHb = sb, aLb = sb + EM_A_T;
        const uint32_t bHb = sb + 2 * EM_A_T, bLb = bHb + EM_B_T;

#pragma unroll
        for (int kh = 0; kh < 2; kh++) {
            const uint32_t kb = kh * 32;
            uint32_t aH[2][4], aL[2][4];
            ldsm_x4(aH[0], aHb + aOff + kb);
            ldsm_x4(aH[1], aHb + aOff + 16 * EM_RS + kb);
            ldsm_x4(aL[0], aLb + aOff + kb);
            ldsm_x4(aL[1], aLb + aOff + 16 * EM_RS + kb);
#pragma unroll
            for (int nt = 0; nt < 4; nt++) {
                uint32_t bH[2], bL[2];
                ldsm_x2(bH, bHb + bOff + nt * 8 * EM_RS + kb);
                ldsm_x2(bL, bLb + bOff + nt * 8 * EM_RS + kb);
#pragma unroll
                for (int mt = 0; mt < 2; mt++) {
                    mma16816(acc[mt][nt], aH[mt], bH);
                    mma16816(acc[mt][nt], aH[mt], bL);
                    mma16816(acc[mt][nt], aL[mt], bH);
                }
            }
        }
    }

    float* __restrict__ pOut = g_pret + (size_t)d * NPOS;
    const int g  = lane >> 2;
    const int kc = (lane & 3) * 2;
#pragma unroll
    for (int mt = 0; mt < 2; mt++) {
#pragma unroll
        for (int nt = 0; nt < 4; nt++) {
            const int i = i0 + wm * 32 + mt * 16 + g;
            const int k = k0 + wn * 32 + nt * 8 + kc;
            *reinterpret_cast<float2*>(&pOut[(size_t)i * NRES + k]) =
                make_float2(acc[mt][nt][0], acc[mt][nt][1]);
            *reinterpret_cast<float2*>(&pOut[(size_t)(i + 8) * NRES + k]) =
                make_float2(acc[mt][nt][2], acc[mt][nt][3]);
        }
    }
}

// ---------------------------------------------------------------------------
// K5: fused gate+output projection.
// Per stage s (K = d chunk of 32): cp.async pret fp32 [32d x 64pos] and
// gate fp32 [64pos x 32d] (both coalesced); build the bf16 A-tile in smem:
// A[p][dd] = bsplit(pret[dd][p] * gate[p][dd]) in the standard 80B-row layout;
// then identical ldsm/mma3 path as R13's proj_single3.
// FIXES vs R15: gate row stride padded to 36 floats (144B, 16B-multiple) so
// cp.async/float4 stay aligned; fill_W loops exactly 1024 chunks (was 1280,
// overrunning a 2-entry pointer array and the W slab).
// ---------------------------------------------------------------------------
#define OF_PR_RS   68                            // floats per pret row (64+4 pad), 272B
#define OF_GT_RS   36                            // floats per gate row (32+4 pad), 144B
#define OF_PR_SZ   (32 * OF_PR_RS * 4)           // 8704
#define OF_GT_SZ   (64 * OF_GT_RS * 4)           // 9216
#define OF_F32_ST  (OF_PR_SZ + OF_GT_SZ)         // 17920
#define OF_A_OFF   (2 * OF_F32_ST)               // 35840
#define OF_A_SZ    (64 * PJ_RS)                  // 5120
#define OF_W_OFF   (OF_A_OFF + 2 * OF_A_SZ)      // 46080
#define OF_W_ST    (2 * PJ_B_T)                  // 20480
#define OF_SMEM    (OF_W_OFF + 2 * OF_W_ST)      // 87040

template<int WIDX>
__global__ __launch_bounds__(256, 2) void proj_out_fused(
    const float* __restrict__ bias, float* __restrict__ dst)
{
    extern __shared__ char smem[];
    const uint32_t sbase = (uint32_t)__cvta_generic_to_shared(smem);
    const int t = threadIdx.x, lane = t & 31, wid = t >> 5;
    const int wm = wid & 3, wn = wid >> 2;
    const int pos0 = blockIdx.x * 64;

    const __nv_bfloat16* __restrict__ wh = g_Wth + WIDX * (DCH*DCH);
    const __nv_bfloat16* __restrict__ wl = g_Wtl + WIDX * (DCH*DCH);

    float acc[8][4];
#pragma unroll
    for (int nt = 0; nt < 8; nt++)
#pragma unroll
        for (int c = 0; c < 4; c++) acc[nt][c] = 0.f;

    auto fill_f32 = [&](int s) {
        char* fb = smem + (s & 1) * OF_F32_ST;
        const int d0 = s * 32;
#pragma unroll
        for (int q = 0; q < 2; q++) {   // pret: 512 chunks of 16B
            int c = t + q * 256;
            int dr = c >> 4, ch = c & 15;
            cp16(fb + dr * (OF_PR_RS * 4) + ch * 16,
                 g_pret + (size_t)(d0 + dr) * NPOS + pos0 + ch * 4);
        }
#pragma unroll
        for (int q = 0; q < 2; q++) {   // gate: 512 chunks of 16B
            int c = t + q * 256;
            int pr = c >> 3, ch = c & 7;
            cp16(fb + OF_PR_SZ + pr * (OF_GT_RS * 4) + ch * 16,
                 g_gate + (size_t)(pos0 + pr) * DCH + d0 + ch * 4);
        }
    };
    auto fill_W = [&](int s) {
        char* wb = smem + OF_W_OFF + (s & 1) * OF_W_ST;
        const __nv_bfloat16* wsrc[2] = {wh, wl};
#pragma unroll
        for (int q = 0; q < 4; q++) {   // exactly 1024 chunks of 16B
            int c = t + q * 256;
            int m = c >> 9, n = (c >> 2) & 127, col = c & 3;
            cp16(wb + m * PJ_B_T + n * PJ_RS + col * 16,
                 wsrc[m] + n * DCH + s * 32 + col * 8);
        }
    };

    fill_f32(0); fill_W(0); asm volatile("cp.async.commit_group;");
    fill_f32(1); fill_W(1); asm volatile("cp.async.commit_group;");

    const uint32_t aOff = (uint32_t)(OF_A_OFF + (wm * 16 + (lane & 15)) * PJ_RS
                                     + ((lane >> 4) << 4));
    const uint32_t bOff = (uint32_t)((wn * 64 + (lane & 15)) * PJ_RS + ((lane >> 4) << 4));

    for (int s = 0; s < 4; s++) {
        asm volatile("cp.async.wait_group 1;");
        __syncthreads();                  // fp32 + W of stage s resident; sA free

        // Build A tile: A[p][dd] = bsplit(pret[dd][p] * gate[p][dd])
        {
            const float* fp = reinterpret_cast<const float*>(smem + (s & 1) * OF_F32_ST);
            const float* fg = fp + OF_PR_SZ / 4;
            __nv_bfloat16* sAh = reinterpret_cast<__nv_bfloat16*>(smem + OF_A_OFF);
            __nv_bfloat16* sAl = sAh + OF_A_SZ / 2;
            const int p = t >> 2, dg = (t & 3) * 8;
            float4 g0 = *reinterpret_cast<const float4*>(&fg[p * OF_GT_RS + dg]);
            float4 g1 = *reinterpret_cast<const float4*>(&fg[p * OF_GT_RS + dg + 4]);
            float gv[8] = {g0.x, g0.y, g0.z, g0.w, g1.x, g1.y, g1.z, g1.w};
            uint32_t whv[4], wlv[4];
#pragma unroll
            for (int q = 0; q < 4; q++) {
                float v0 = fp[(dg + 2*q    ) * OF_PR_RS + p] * gv[2*q];
                float v1 = fp[(dg + 2*q + 1) * OF_PR_RS + p] * gv[2*q + 1];
                __nv_bfloat16 h0, l0, h1, l1;
                bsplit(v0, h0, l0); bsplit(v1, h1, l1);
                whv[q] = pack2(h0, h1);
                wlv[q] = pack2(l0, l1);
            }
            *reinterpret_cast<uint4*>(&sAh[p * 40 + dg]) =
                make_uint4(whv[0], whv[1], whv[2], whv[3]);
            *reinterpret_cast<uint4*>(&sAl[p * 40 + dg]) =
                make_uint4(wlv[0], wlv[1], wlv[2], wlv[3]);
        }
        __syncthreads();                  // sA ready; fp32 buffer s&1 free
        if (s + 2 < 4) fill_f32(s + 2);

        const uint32_t wbB = sbase + OF_W_OFF + (s & 1) * OF_W_ST;
#pragma unroll
        for (int kh = 0; kh < 2; kh++) {
            uint32_t aH[4], aL[4];
            ldsm_x4(aH, sbase + aOff + kh * 32);
            ldsm_x4(aL, sbase + OF_A_SZ + aOff + kh * 32);
#pragma unroll
            for (int ntp = 0; ntp < 4; ntp++) {
                const uint32_t bo = bOff + ntp * 16 * PJ_RS + kh * 32;
                uint32_t bH[4], bL[4];
                ldsm_x4(bH, wbB + bo);
                ldsm_x4(bL, wbB + PJ_B_T + bo);
                mma3(acc[2*ntp  ], aH, aL, bH[0], bH[2], bL[0], bL[2]);
                mma3(acc[2*ntp+1], aH, aL, bH[1], bH[3], bL[1], bL[3]);
            }
        }
        __syncthreads();                  // all warps done with W s&1 (and sA)
        if (s + 2 < 4) fill_W(s + 2);
        asm volatile("cp.async.commit_group;");   // one group per stage (uniform)
    }

    const int g  = lane >> 2;
    const int kc = (lane & 3) * 2;
    const int ra = pos0 + wm * 16 + g, rb = ra + 8;
#pragma unroll
    for (int nt = 0; nt < 8; nt++) {
        const int col = wn * 64 + nt * 8 + kc;
        const float b0 = bias[col], b1 = bias[col + 1];
        float2 oa, ob;
        oa.x = acc[nt][0] + b0; oa.y = acc[nt][1] + b1;
        ob.x = acc[nt][2] + b0; ob.y = acc[nt][3] + b1;
        *reinterpret_cast<float2*>(&dst[(size_t)ra * DCH + col]) = oa;
        *reinterpret_cast<float2*>(&dst[(size_t)rb * DCH + col]) = ob;
    }
}

// ---------------------------------------------------------------------------
extern "C" void kernel_launch(void* const* d_in, const int* in_sizes, int n_in,
                              void* d_out, int out_size)
{
    (void)in_sizes; (void)n_in; (void)out_size;
    const float* pair = (const float*)d_in[0];
    const float* mask = (const float*)d_in[1];
    const float* ln_g = (const float*)d_in[2];
    const float* ln_b = (const float*)d_in[3];
    const float* w_lp = (const float*)d_in[4];
    const float* b_lp = (const float*)d_in[5];
    const float* w_lg = (const float*)d_in[6];
    const float* b_lg = (const float*)d_in[7];
    const float* w_rp = (const float*)d_in[8];
    const float* b_rp = (const float*)d_in[9];
    const float* w_rg = (const float*)d_in[10];
    const float* b_rg = (const float*)d_in[11];
    const float* w_g  = (const float*)d_in[12];
    const float* b_g  = (const float*)d_in[13];
    const float* w_o  = (const float*)d_in[14];
    const float* b_o  = (const float*)d_in[15];
    float* out = (float*)d_out;

    cudaFuncSetAttribute(einsum_mma_kernel,
                         cudaFuncAttributeMaxDynamicSharedMemorySize, EM_SMEM);
    cudaFuncSetAttribute(proj_dual_mma<0,1,0>,
                         cudaFuncAttributeMaxDynamicSharedMemorySize, PJ_SMEM_D);
    cudaFuncSetAttribute(proj_dual_mma<2,3,1>,
                         cudaFuncAttributeMaxDynamicSharedMemorySize, PJ_SMEM_D);
    cudaFuncSetAttribute(proj_gate1_mma<4>,
                         cudaFuncAttributeMaxDynamicSharedMemorySize, PJ_SMEM_S1);
    cudaFuncSetAttribute(proj_out_fused<5>,
                         cudaFuncAttributeMaxDynamicSharedMemorySize, OF_SMEM);

    prep_weights<<<6, 256>>>(w_lp, w_lg, w_rp, w_rg, w_g, w_o);
    ln_split_kernel<<<NPOS / 8, 256>>>(pair, ln_g, ln_b);
    proj_dual_mma<0,1,0><<<NPOS / 64, 256, PJ_SMEM_D>>>(b_lp, b_lg, mask);
    proj_dual_mma<2,3,1><<<NPOS / 64, 256, PJ_SMEM_D>>>(b_rp, b_rg, mask);
    proj_gate1_mma<4><<<NPOS / 64, 256, PJ_SMEM_S1>>>(b_g);
    einsum_mma_kernel<<<4096, 256, EM_SMEM>>>();
    proj_out_fused<5><<<NPOS / 64, 256, OF_SMEM>>>(b_o, out);
}